// round 8
// baseline (speedup 1.0000x reference)
#include <cuda_runtime.h>

#define NB   32
#define DD   256
#define MMs  784
#define CINc 2048
#define MAT  (DD*DD)          // 65536
#define BMAT (NB*MAT)         // 2,097,152
#define KC   16               // K chunk (FFMA kernels)
#define MM_SMEM 73728         // 4 * 128*36 floats * 4B

// Scratch (device globals; no allocation anywhere)
__device__ float g_y[NB*DD*MMs];      // BN'd ReLU'd activations [b][d][m]
__device__ float g_mats[9u*BMAT];     // 9 batched 256x256 buffers
__device__ float g_small[16384];
// [0,256) bn_mean [256,512) bn_rstd [512,8704) rowmean
// [8704,8736) tr0 [8736,8768) tr_now [8768] jc [8772,8836) trp (NB*2)

// ---------------------------------------------------------------------------
__device__ __forceinline__ float warpReduce(float v) {
    #pragma unroll
    for (int o = 16; o; o >>= 1) v += __shfl_down_sync(0xffffffffu, v, o);
    return v;
}

__device__ __forceinline__ void tilemap(int t, int& ti, int& tj) {
    if (t < 4)      { ti = 0; tj = t; }
    else if (t < 7) { ti = 1; tj = t - 3; }
    else if (t < 9) { ti = 2; tj = t - 5; }
    else            { ti = 3; tj = 3; }
}

__device__ __forceinline__ float sice_f(float L, float g12, float dec)
{
    float lp = fmaxf(L, 0.f);
    float lm = fmaxf(-L, 0.f);
    lp = fmaxf(lp - dec * (g12 + 0.07f), 0.f);
    lm = fmaxf(lm - dec * (-g12 + 0.07f), 0.f);
    return lp - lm;
}

// ---------------------------------------------------------------------------
// tf32 helpers
// ---------------------------------------------------------------------------
__device__ __forceinline__ float tf32r(float x) {
    unsigned u;
    asm("cvt.rna.tf32.f32 %0, %1;" : "=r"(u) : "f"(x));
    return __uint_as_float(u);
}
__device__ __forceinline__ void split4(float4 x, float4& hi, float4& lo) {
    hi.x = tf32r(x.x); lo.x = tf32r(x.x - hi.x);
    hi.y = tf32r(x.y); lo.y = tf32r(x.y - hi.y);
    hi.z = tf32r(x.z); lo.z = tf32r(x.z - hi.z);
    hi.w = tf32r(x.w); lo.w = tf32r(x.w - hi.w);
}
__device__ __forceinline__ void mma8(float* c, const unsigned* a, const unsigned* b) {
    asm volatile(
        "mma.sync.aligned.m16n8k8.row.col.f32.tf32.tf32.f32 "
        "{%0,%1,%2,%3}, {%4,%5,%6,%7}, {%8,%9}, {%0,%1,%2,%3};"
        : "+f"(c[0]), "+f"(c[1]), "+f"(c[2]), "+f"(c[3])
        : "r"(a[0]), "r"(a[1]), "r"(a[2]), "r"(a[3]), "r"(b[0]), "r"(b[1]));
}

// ===========================================================================
// mm_gemm: batched D(128x128 tile) = A(128,K=256) x B^T  (B rows fed K-major;
// all operands symmetric so this equals A@B).  tf32 split-2, mma.sync m16n8k8.
// z<NB: (A1,B1,D1); z>=NB: (A2,B2,D2).
// epi 0: D=P; 1: D=1.5I-0.5P; 2: D=P*rsqrt(tr_now); 3: fused SICE on D(=L).
// Diagonal tiles (mi==nj) write trace partials trp[b*2+mi] when trp!=null.
// grid (2, 2, NB or 2NB), 256 threads, MM_SMEM dynamic smem.
// Smem layout (floats, pitch 36/row): Ah[128][36] Al Bh Bl.
// ===========================================================================
__global__ __launch_bounds__(256, 1) void mm_gemm(
    const float* __restrict__ A1, const float* __restrict__ B1, float* __restrict__ D1,
    const float* __restrict__ A2, const float* __restrict__ B2, float* __restrict__ D2,
    const float* __restrict__ tr_now, int epi, const float* __restrict__ Cn, float dec,
    float* __restrict__ trp)
{
    extern __shared__ float Sf[];
    float* const sAh = Sf;
    float* const sAl = Sf + 4608;
    float* const sBh = Sf + 9216;
    float* const sBl = Sf + 13824;

    const int z = blockIdx.z;
    const int b = z & (NB - 1);
    const float* Ab = ((z >= NB) ? A2 : A1) + (size_t)b * MAT;
    const float* Bb = ((z >= NB) ? B2 : B1) + (size_t)b * MAT;
    float* Dp = ((z >= NB) ? D2 : D1) + (size_t)b * MAT;
    const int mi = blockIdx.y, nj = blockIdx.x;
    const int m0 = mi * 128, n0 = nj * 128;

    const int tid = threadIdx.x;
    const int wid = tid >> 5, lane = tid & 31;
    const int g = lane >> 2, t = lane & 3;
    const int wm = wid >> 2, wn = wid & 3;          // warp grid 2 (m) x 4 (n)
    const int mw = wm * 64, nw = wn * 32;

    const int srow = tid >> 3, sq = tid & 7;        // staging: row 0..31 (+32p), q 0..7

    float acc[4][4][4] = {};

    for (int c0 = 0; c0 < 256; c0 += 32) {          // K chunks of 32
        // ---- stage chunk: A/B 128x32 -> hi/lo smem ----
        #pragma unroll
        for (int p = 0; p < 4; p++) {
            const int row = srow + p * 32;
            float4 hi, lo;
            float4 av = *(const float4*)(Ab + (size_t)(m0 + row) * DD + c0 + sq * 4);
            split4(av, hi, lo);
            *(float4*)(sAh + row * 36 + sq * 4) = hi;
            *(float4*)(sAl + row * 36 + sq * 4) = lo;
            float4 bv = *(const float4*)(Bb + (size_t)(n0 + row) * DD + c0 + sq * 4);
            split4(bv, hi, lo);
            *(float4*)(sBh + row * 36 + sq * 4) = hi;
            *(float4*)(sBl + row * 36 + sq * 4) = lo;
        }
        __syncthreads();

        // ---- compute: 4 k8-steps ----
        #pragma unroll
        for (int ks = 0; ks < 4; ks++) {
            const int k = ks * 8;
            unsigned Ah[4][4], Al[4][4], Bh[4][2], Bl[4][2];
            #pragma unroll
            for (int f = 0; f < 4; f++) {
                const int base = (mw + f * 16 + g) * 36 + k + t;
                Ah[f][0] = __float_as_uint(sAh[base]);
                Ah[f][1] = __float_as_uint(sAh[base + 8 * 36]);
                Ah[f][2] = __float_as_uint(sAh[base + 4]);
                Ah[f][3] = __float_as_uint(sAh[base + 8 * 36 + 4]);
                Al[f][0] = __float_as_uint(sAl[base]);
                Al[f][1] = __float_as_uint(sAl[base + 8 * 36]);
                Al[f][2] = __float_as_uint(sAl[base + 4]);
                Al[f][3] = __float_as_uint(sAl[base + 8 * 36 + 4]);
            }
            #pragma unroll
            for (int h = 0; h < 4; h++) {
                const int nb = (nw + h * 8 + g) * 36 + k + t;
                Bh[h][0] = __float_as_uint(sBh[nb]);
                Bh[h][1] = __float_as_uint(sBh[nb + 4]);
                Bl[h][0] = __float_as_uint(sBl[nb]);
                Bl[h][1] = __float_as_uint(sBl[nb + 4]);
            }
            #pragma unroll
            for (int f = 0; f < 4; f++)
                #pragma unroll
                for (int h = 0; h < 4; h++) {
                    mma8(acc[f][h], Ah[f], Bh[h]);
                    mma8(acc[f][h], Ah[f], Bl[h]);
                    mma8(acc[f][h], Al[f], Bh[h]);
                }
        }
        __syncthreads();
    }

    // ---- epilogue ----
    const float rs = (epi == 2) ? rsqrtf(tr_now[b]) : 1.0f;
    const float* Cb = (epi == 3) ? (Cn + (size_t)b * MAT) : nullptr;
    float dsum = 0.f;
    const bool diag = (trp != nullptr) && (mi == nj);
    #pragma unroll
    for (int f = 0; f < 4; f++) {
        const int r0 = m0 + mw + f * 16 + g;
        const int r1 = r0 + 8;
        #pragma unroll
        for (int h = 0; h < 4; h++) {
            const int c = n0 + nw + h * 8 + 2 * t;
            float v[4] = {acc[f][h][0], acc[f][h][1], acc[f][h][2], acc[f][h][3]};
            const int rr[4] = {r0, r0, r1, r1};
            const int cc[4] = {c, c + 1, c, c + 1};
            if (epi == 1) {
                #pragma unroll
                for (int j = 0; j < 4; j++)
                    v[j] = ((rr[j] == cc[j]) ? 1.5f : 0.0f) - 0.5f * v[j];
            } else if (epi == 2) {
                #pragma unroll
                for (int j = 0; j < 4; j++) v[j] *= rs;
            } else if (epi == 3) {
                #pragma unroll
                for (int j = 0; j < 4; j++) {
                    float Lv = Dp[(size_t)rr[j] * DD + cc[j]];
                    float gg = Cb[(size_t)rr[j] * DD + cc[j]] - v[j];
                    v[j] = sice_f(Lv, gg, dec);
                }
            }
            if (diag) {
                #pragma unroll
                for (int j = 0; j < 4; j++)
                    if (rr[j] == cc[j]) dsum += v[j];
            }
            *(float2*)(Dp + (size_t)r0 * DD + c) = make_float2(v[0], v[1]);
            *(float2*)(Dp + (size_t)r1 * DD + c) = make_float2(v[2], v[3]);
        }
    }

    if (diag) {
        __syncthreads();          // smem staging no longer needed
        Sf[tid] = dsum;
        __syncthreads();
        if (tid == 0) {
            float s2 = 0.f;
            for (int u = 0; u < 256; u++) s2 += Sf[u];
            trp[b * 2 + mi] = s2;
        }
    }
}

// ===========================================================================
// FFMA kernels (R5 verbatim): conv, BN, covariance
// ===========================================================================
#define GEMM_COMPUTE(AsB, BsB)                                                 \
    {                                                                          \
        _Pragma("unroll")                                                      \
        for (int kk = 0; kk < KC; kk++) {                                      \
            float4 a0 = *(const float4*)(&(AsB)[kk][tr8 * 8]);                 \
            float4 a1 = *(const float4*)(&(AsB)[kk][tr8 * 8 + 4]);             \
            float4 bv = *(const float4*)(&(BsB)[kk][tc * 4]);                  \
            float ar[8] = {a0.x,a0.y,a0.z,a0.w,a1.x,a1.y,a1.z,a1.w};           \
            float br[4] = {bv.x,bv.y,bv.z,bv.w};                               \
            _Pragma("unroll")                                                  \
            for (int i = 0; i < 8; i++)                                        \
                _Pragma("unroll")                                              \
                for (int j = 0; j < 4; j++)                                    \
                    acc[i][j] = fmaf(ar[i], br[j], acc[i][j]);                 \
        }                                                                      \
    }

__global__ void conv_gemm(
    const float* __restrict__ x, const float* __restrict__ w, float* __restrict__ y)
{
    const int b  = blockIdx.z;
    const int m0 = blockIdx.y * 64;
    const int n0 = blockIdx.x * 64;
    const float* Ap = w;
    const float* Bp = x + (size_t)b * CINc * MMs;
    float* Dp = y + (size_t)b * DD * MMs;

    __shared__ float As[2][KC][68];
    __shared__ float Bs[2][KC][68];
    const int tid = threadIdx.x;
    const int tc = tid & 15, tr8 = tid >> 4;

    float4 pa[2], pb[2];
    float acc[8][4] = {};

    #pragma unroll
    for (int h = 0; h < 2; h++) {
        int fi = tid + 128 * h;
        int row = fi >> 2, q = fi & 3;
        pa[h] = *(const float4*)(Ap + (size_t)(m0 + row) * CINc + q * 4);
        int kr = fi >> 4, nc = fi & 15;
        int col = n0 + nc * 4;
        pb[h] = (col < MMs) ? *(const float4*)(Bp + (size_t)kr * MMs + col)
                            : make_float4(0.f, 0.f, 0.f, 0.f);
    }
    #pragma unroll
    for (int h = 0; h < 2; h++) {
        int fi = tid + 128 * h;
        int row = fi >> 2, q = fi & 3;
        As[0][q*4+0][row] = pa[h].x; As[0][q*4+1][row] = pa[h].y;
        As[0][q*4+2][row] = pa[h].z; As[0][q*4+3][row] = pa[h].w;
        int kr = fi >> 4, nc = fi & 15;
        *(float4*)&Bs[0][kr][nc*4] = pb[h];
    }
    __syncthreads();

    const int NCH = CINc / KC;
    for (int ch = 0; ch < NCH; ch++) {
        const int buf = ch & 1;
        if (ch + 1 < NCH) {
            const int k0 = (ch + 1) * KC;
            #pragma unroll
            for (int h = 0; h < 2; h++) {
                int fi = tid + 128 * h;
                int row = fi >> 2, q = fi & 3;
                pa[h] = *(const float4*)(Ap + (size_t)(m0 + row) * CINc + k0 + q * 4);
                int kr = fi >> 4, nc = fi & 15;
                int col = n0 + nc * 4;
                pb[h] = (col < MMs) ? *(const float4*)(Bp + (size_t)(k0 + kr) * MMs + col)
                                    : make_float4(0.f, 0.f, 0.f, 0.f);
            }
        }
        GEMM_COMPUTE(As[buf], Bs[buf]);
        if (ch + 1 < NCH) {
            const int nb = buf ^ 1;
            #pragma unroll
            for (int h = 0; h < 2; h++) {
                int fi = tid + 128 * h;
                int row = fi >> 2, q = fi & 3;
                As[nb][q*4+0][row] = pa[h].x; As[nb][q*4+1][row] = pa[h].y;
                As[nb][q*4+2][row] = pa[h].z; As[nb][q*4+3][row] = pa[h].w;
                int kr = fi >> 4, nc = fi & 15;
                *(float4*)&Bs[nb][kr][nc*4] = pb[h];
            }
            __syncthreads();
        }
    }

    #pragma unroll
    for (int i = 0; i < 8; i++) {
        const int r = m0 + tr8 * 8 + i;
        const int c = n0 + tc * 4;
        if (c < MMs)
            *(float4*)(Dp + (size_t)r * MMs + c) =
                make_float4(acc[i][0], acc[i][1], acc[i][2], acc[i][3]);
    }
}

__global__ void bn_stats(const float* __restrict__ y, float* __restrict__ mean,
                         float* __restrict__ rstd)
{
    const int d = blockIdx.x;
    const int t = threadIdx.x;
    float s = 0.f, s2 = 0.f;
    for (int b = 0; b < NB; b++) {
        const float* p = y + (size_t)b * DD * MMs + (size_t)d * MMs;
        for (int m = t; m < MMs; m += 256) { float v = p[m]; s += v; s2 = fmaf(v, v, s2); }
    }
    __shared__ float sh1[8], sh2[8];
    const int lane = t & 31, wid = t >> 5;
    s = warpReduce(s); s2 = warpReduce(s2);
    if (lane == 0) { sh1[wid] = s; sh2[wid] = s2; }
    __syncthreads();
    if (wid == 0) {
        s  = (lane < 8) ? sh1[lane] : 0.f;
        s2 = (lane < 8) ? sh2[lane] : 0.f;
        s = warpReduce(s); s2 = warpReduce(s2);
        if (lane == 0) {
            const float N = (float)(NB * MMs);
            float mu  = s / N;
            float var = s2 / N - mu * mu;
            mean[d] = mu;
            rstd[d] = rsqrtf(var + 1e-5f);
        }
    }
}

__global__ void bn_apply(float* __restrict__ y, const float* __restrict__ mean,
                         const float* __restrict__ rstd, const float* __restrict__ gamma,
                         const float* __restrict__ beta, float* __restrict__ rowmean)
{
    const int bd = blockIdx.x;
    const int d  = bd & (DD - 1);
    float* p = y + (size_t)bd * MMs;
    const float mu = mean[d], rs = rstd[d], g = gamma[d], be = beta[d];
    const int t = threadIdx.x;
    float s = 0.f;
    for (int m = t; m < MMs; m += 256) {
        float v = fmaf((p[m] - mu) * rs, g, be);
        v = fmaxf(v, 0.f);
        p[m] = v;
        s += v;
    }
    __shared__ float sh[8];
    const int lane = t & 31, wid = t >> 5;
    s = warpReduce(s);
    if (lane == 0) sh[wid] = s;
    __syncthreads();
    if (wid == 0) {
        s = (lane < 8) ? sh[lane] : 0.f;
        s = warpReduce(s);
        if (lane == 0) rowmean[bd] = s * (1.0f / MMs);
    }
}

__global__ void cov_sym(
    const float* __restrict__ y, const float* __restrict__ rowmean, float* __restrict__ C)
{
    const int b = blockIdx.z;
    int ti, tj; tilemap(blockIdx.x, ti, tj);
    const int i0 = ti * 64, j0 = tj * 64;
    const float* Yb = y + (size_t)b * DD * MMs;

    __shared__ float Is[2][KC][68];
    __shared__ float Js[2][KC][68];
    const int tid = threadIdx.x;
    const int tc = tid & 15, tr8 = tid >> 4;

    float4 pa[2], pb[2];
    float acc[8][4] = {};

    #pragma unroll
    for (int h = 0; h < 2; h++) {
        int fi = tid + 128 * h;
        int row = fi >> 2, q = fi & 3;
        pa[h] = *(const float4*)(Yb + (size_t)(i0 + row) * MMs + q * 4);
        pb[h] = *(const float4*)(Yb + (size_t)(j0 + row) * MMs + q * 4);
    }
    #pragma unroll
    for (int h = 0; h < 2; h++) {
        int fi = tid + 128 * h;
        int row = fi >> 2, q = fi & 3;
        Is[0][q*4+0][row] = pa[h].x; Is[0][q*4+1][row] = pa[h].y;
        Is[0][q*4+2][row] = pa[h].z; Is[0][q*4+3][row] = pa[h].w;
        Js[0][q*4+0][row] = pb[h].x; Js[0][q*4+1][row] = pb[h].y;
        Js[0][q*4+2][row] = pb[h].z; Js[0][q*4+3][row] = pb[h].w;
    }
    __syncthreads();

    const int NCH = MMs / KC;
    for (int ch = 0; ch < NCH; ch++) {
        const int buf = ch & 1;
        if (ch + 1 < NCH) {
            const int k0 = (ch + 1) * KC;
            #pragma unroll
            for (int h = 0; h < 2; h++) {
                int fi = tid + 128 * h;
                int row = fi >> 2, q = fi & 3;
                pa[h] = *(const float4*)(Yb + (size_t)(i0 + row) * MMs + k0 + q * 4);
                pb[h] = *(const float4*)(Yb + (size_t)(j0 + row) * MMs + k0 + q * 4);
            }
        }
        GEMM_COMPUTE(Is[buf], Js[buf]);
        if (ch + 1 < NCH) {
            const int nb = buf ^ 1;
            #pragma unroll
            for (int h = 0; h < 2; h++) {
                int fi = tid + 128 * h;
                int row = fi >> 2, q = fi & 3;
                Is[nb][q*4+0][row] = pa[h].x; Is[nb][q*4+1][row] = pa[h].y;
                Is[nb][q*4+2][row] = pa[h].z; Is[nb][q*4+3][row] = pa[h].w;
                Js[nb][q*4+0][row] = pb[h].x; Js[nb][q*4+1][row] = pb[h].y;
                Js[nb][q*4+2][row] = pb[h].z; Js[nb][q*4+3][row] = pb[h].w;
            }
            __syncthreads();
        }
    }

    const float invM = 1.0f / (float)MMs;
    const float* mu = rowmean + b * DD;
    float* Cb = C + (size_t)b * MAT;
    #pragma unroll
    for (int i = 0; i < 8; i++) {
        const int r = i0 + tr8 * 8 + i;
        const float mi = mu[r];
        const int c0 = j0 + tc * 4;
        float v[4];
        #pragma unroll
        for (int j = 0; j < 4; j++) v[j] = acc[i][j] * invM - mi * mu[c0 + j];
        *(float4*)(Cb + (size_t)r * DD + c0) = make_float4(v[0], v[1], v[2], v[3]);
        if (ti != tj) {
            #pragma unroll
            for (int j = 0; j < 4; j++) Cb[(size_t)(c0+j) * DD + r] = v[j];
        }
    }
}

// ---------------------------------------------------------------------------
// small kernels
// ---------------------------------------------------------------------------
__global__ void tracek0(const float* __restrict__ X, const float* __restrict__ jitter,
                        float* __restrict__ tr0, float* __restrict__ jcp)
{
    const int b = blockIdx.x;
    const int t = threadIdx.x;
    float v = X[(size_t)b * MAT + t * 257];
    float jt = 1e-10f + 1e-9f * jitter[t];
    __shared__ float sh[8], shj[8];
    const int lane = t & 31, wid = t >> 5;
    v = warpReduce(v); jt = warpReduce(jt);
    if (lane == 0) { sh[wid] = v; shj[wid] = jt; }
    __syncthreads();
    if (wid == 0) {
        v  = (lane < 8) ? sh[lane]  : 0.f;
        jt = (lane < 8) ? shj[lane] : 0.f;
        v = warpReduce(v); jt = warpReduce(jt);
        if (lane == 0) {
            tr0[b] = v;
            if (b == 0) *jcp = jt;
        }
    }
}

__global__ void scalek(float* __restrict__ C, const float* __restrict__ tr0)
{
    const int idx = blockIdx.x * 256 + threadIdx.x;
    C[idx] *= (1.0f / tr0[idx >> 16]);
}

// A = (S + Ij)/t;  ZY0 = 1.5I - 0.5A ; t from 2 trace partials (+jc) or 1+jc
__global__ void prep_ns(const float* __restrict__ Sm, const float* __restrict__ jitter,
                        const float* __restrict__ trp, const float* __restrict__ jcp,
                        float* __restrict__ A, float* __restrict__ ZY,
                        float* __restrict__ tr_now)
{
    const int idx = blockIdx.x * 256 + threadIdx.x;
    const int b = idx >> 16, rc = idx & 65535, r = rc >> 8, c = rc & 255;
    const float jc = *jcp;
    float t;
    if (trp != nullptr) t = trp[b*2+0] + trp[b*2+1] + jc;
    else                t = 1.0f + jc;
    float v = Sm[idx];
    if (r == c) v += 1e-10f + 1e-9f * jitter[r];
    float a = v * (1.0f / t);
    A[idx] = a;
    ZY[idx] = (r == c ? 1.5f : 0.0f) - 0.5f * a;
    if (rc == 0) tr_now[b] = t;
}

__global__ void gather_out(const float* __restrict__ L, const float* __restrict__ trp,
                           float* __restrict__ out)
{
    const int b = blockIdx.y, i = blockIdx.x, j = threadIdx.x;
    if (j < i) return;
    const float t = trp[b*2+0] + trp[b*2+1];
    const float s = rsqrtf(t);
    const int k = i * 256 - (i * (i - 1)) / 2 + (j - i);
    out[(size_t)b * 32896 + k] = L[(size_t)b * MAT + i * 256 + j] * s;
}

// ---------------------------------------------------------------------------
// Host orchestration
// ---------------------------------------------------------------------------
static void run_inv(const float* Sm, const float* jitter, const float* trp_in,
                    float* zz, float* tr_now, const float* jcp,
                    float* A, float* Y, float* Z, float* Y2, float* Z2, float* ZYt)
{
    const dim3 g1(2, 2, NB);
    const dim3 g2(2, 2, 2 * NB);
    const float* FN = nullptr;
    float* FNm = nullptr;
    prep_ns<<<BMAT / 256, 256>>>(Sm, jitter, trp_in, jcp, A, Z, tr_now);   // Z = ZY0
    mm_gemm<<<g1, 256, MM_SMEM>>>(A, Z, Y, FN, FN, FNm, tr_now, 0, FN, 0.f, FNm);
    float *Yc = Y, *Zc = Z, *Ya = Y2, *Za = Z2;
    for (int it = 0; it < 5; it++) {
        mm_gemm<<<g1, 256, MM_SMEM>>>(Zc, Yc, ZYt, FN, FN, FNm, tr_now, 1, FN, 0.f, FNm);
        mm_gemm<<<g2, 256, MM_SMEM>>>(Yc, ZYt, Ya, ZYt, Zc, Za, tr_now, 0, FN, 0.f, FNm);
        float* t1 = Yc; Yc = Ya; Ya = t1;
        float* t2 = Zc; Zc = Za; Za = t2;
    }
    mm_gemm<<<g1, 256, MM_SMEM>>>(Zc, Yc, ZYt, FN, FN, FNm, tr_now, 1, FN, 0.f, FNm);
    mm_gemm<<<g1, 256, MM_SMEM>>>(ZYt, Zc, zz, FN, FN, FNm, tr_now, 2, FN, 0.f, FNm);
}

extern "C" void kernel_launch(void* const* d_in, const int* in_sizes, int n_in,
                              void* d_out, int out_size)
{
    (void)in_sizes; (void)n_in; (void)out_size;
    const float* x      = (const float*)d_in[0];
    const float* w      = (const float*)d_in[1];
    const float* gamma  = (const float*)d_in[2];
    const float* beta   = (const float*)d_in[3];
    const float* jitter = (const float*)d_in[4];
    float* out = (float*)d_out;

    cudaFuncSetAttribute(mm_gemm, cudaFuncAttributeMaxDynamicSharedMemorySize, MM_SMEM);

    float *y, *mats, *small;
    cudaGetSymbolAddress((void**)&y, g_y);
    cudaGetSymbolAddress((void**)&mats, g_mats);
    cudaGetSymbolAddress((void**)&small, g_small);

    float* Cn  = mats + 0u * BMAT;
    float* A   = mats + 1u * BMAT;
    float* Y   = mats + 2u * BMAT;
    float* Z   = mats + 3u * BMAT;
    float* Y2  = mats + 4u * BMAT;
    float* Z2  = mats + 5u * BMAT;
    float* ZYt = mats + 6u * BMAT;
    float* zz  = mats + 7u * BMAT;
    float* LLT = mats + 8u * BMAT;

    float* bn_mean = small;
    float* bn_rstd = small + 256;
    float* rowmean = small + 512;
    float* tr0     = small + 8704;
    float* tr_now  = small + 8736;
    float* jcp     = small + 8768;
    float* trp     = small + 8772;

    const dim3 g1(2, 2, NB);
    const float* FN = nullptr;
    float* FNm = nullptr;

    // Stage 1: conv + BN + ReLU
    conv_gemm<<<dim3(13, 4, NB), 128>>>(x, w, y);
    bn_stats<<<DD, 256>>>(y, bn_mean, bn_rstd);
    bn_apply<<<NB * DD, 256>>>(y, bn_mean, bn_rstd, gamma, beta, rowmean);

    // Stage 2: covariance + trace normalize (Cn == normalized C == sym_C)
    cov_sym<<<dim3(10, 1, NB), 128>>>(y, rowmean, Cn);
    tracek0<<<NB, 256>>>(Cn, jitter, tr0, jcp);
    scalek<<<BMAT / 256, 256>>>(Cn, tr0);

    // Stage 3: LLT = inv_sqrtm(Cn + Ij)^2 ; tr(Cn+Ij) = 1 + jc analytically
    run_inv(Cn, jitter, nullptr, zz, tr_now, jcp, A, Y, Z, Y2, Z2, ZYt);
    mm_gemm<<<g1, 256, MM_SMEM>>>(zz, zz, LLT, FN, FN, FNm, tr_now, 0, FN, 0.f, trp);

    // Stage 4: SICE loop (i=2 has dec==0 -> exact identity, skipped)
    for (int i = 0; i < 2; i++) {
        run_inv(LLT, jitter, trp, zz, tr_now, jcp, A, Y, Z, Y2, Z2, ZYt);
        const float dec = 5.0f * (1.0f - (float)i / 2.0f);
        mm_gemm<<<g1, 256, MM_SMEM>>>(zz, zz, LLT, FN, FN, FNm, tr_now, 3, Cn, dec, trp);
    }

    // Stage 5: triuvec with trace from final epi3 partials
    gather_out<<<dim3(DD, NB), 256>>>(LLT, trp, out);
}

// round 9
// speedup vs baseline: 1.1838x; 1.1838x over previous
#include <cuda_runtime.h>

#define NB   32
#define DD   256
#define MMs  784
#define CINc 2048
#define MAT  (DD*DD)          // 65536
#define BMAT (NB*MAT)         // 2,097,152
#define KC   16               // K chunk (FFMA kernels)
#define STG  18432            // floats per mma stage (4 arrays of 4608)
#define MM_SMEM 147456        // 2 stages * 18432 floats * 4B

// Scratch (device globals; no allocation anywhere)
__device__ float g_y[NB*DD*MMs];      // BN'd ReLU'd activations [b][d][m]
__device__ float g_mats[9u*BMAT];     // 9 batched 256x256 buffers
__device__ float g_small[16384];
// [0,256) bn_mean [256,512) bn_rstd [512,8704) rowmean
// [8704,8736) tr0 [8736,8768) tr_now [8768] jc [8772,8836) trp (NB*2)

// ---------------------------------------------------------------------------
__device__ __forceinline__ float warpReduce(float v) {
    #pragma unroll
    for (int o = 16; o; o >>= 1) v += __shfl_down_sync(0xffffffffu, v, o);
    return v;
}

__device__ __forceinline__ void tilemap(int t, int& ti, int& tj) {
    if (t < 4)      { ti = 0; tj = t; }
    else if (t < 7) { ti = 1; tj = t - 3; }
    else if (t < 9) { ti = 2; tj = t - 5; }
    else            { ti = 3; tj = 3; }
}

__device__ __forceinline__ float sice_f(float L, float g12, float dec)
{
    float lp = fmaxf(L, 0.f);
    float lm = fmaxf(-L, 0.f);
    lp = fmaxf(lp - dec * (g12 + 0.07f), 0.f);
    lm = fmaxf(lm - dec * (-g12 + 0.07f), 0.f);
    return lp - lm;
}

// ---------------------------------------------------------------------------
// tf32 helpers
// ---------------------------------------------------------------------------
__device__ __forceinline__ float tf32r(float x) {
    unsigned u;
    asm("cvt.rna.tf32.f32 %0, %1;" : "=r"(u) : "f"(x));
    return __uint_as_float(u);
}
__device__ __forceinline__ void split4(float4 x, float4& hi, float4& lo) {
    hi.x = tf32r(x.x); lo.x = tf32r(x.x - hi.x);
    hi.y = tf32r(x.y); lo.y = tf32r(x.y - hi.y);
    hi.z = tf32r(x.z); lo.z = tf32r(x.z - hi.z);
    hi.w = tf32r(x.w); lo.w = tf32r(x.w - hi.w);
}
__device__ __forceinline__ void mma8(float* c, const unsigned* a, const unsigned* b) {
    asm volatile(
        "mma.sync.aligned.m16n8k8.row.col.f32.tf32.tf32.f32 "
        "{%0,%1,%2,%3}, {%4,%5,%6,%7}, {%8,%9}, {%0,%1,%2,%3};"
        : "+f"(c[0]), "+f"(c[1]), "+f"(c[2]), "+f"(c[3])
        : "r"(a[0]), "r"(a[1]), "r"(a[2]), "r"(a[3]), "r"(b[0]), "r"(b[1]));
}

// fragment gather + 48 MMAs for one 32-wide K chunk (4 k8-steps).
// Needs in scope: mw, nw, g, t, acc[4][4][4]; pointers sAh/sAl/sBh/sBl (pitch 36).
#define FRAG_COMPUTE(sAh, sAl, sBh, sBl)                                       \
    _Pragma("unroll")                                                          \
    for (int ks = 0; ks < 4; ks++) {                                           \
        const int k = ks * 8;                                                  \
        unsigned Ah[4][4], Al[4][4], Bh[4][2], Bl[4][2];                       \
        _Pragma("unroll")                                                      \
        for (int f = 0; f < 4; f++) {                                          \
            const int base = (mw + f * 16 + g) * 36 + k + t;                   \
            Ah[f][0] = __float_as_uint((sAh)[base]);                           \
            Ah[f][1] = __float_as_uint((sAh)[base + 8 * 36]);                  \
            Ah[f][2] = __float_as_uint((sAh)[base + 4]);                       \
            Ah[f][3] = __float_as_uint((sAh)[base + 8 * 36 + 4]);              \
            Al[f][0] = __float_as_uint((sAl)[base]);                           \
            Al[f][1] = __float_as_uint((sAl)[base + 8 * 36]);                  \
            Al[f][2] = __float_as_uint((sAl)[base + 4]);                       \
            Al[f][3] = __float_as_uint((sAl)[base + 8 * 36 + 4]);              \
        }                                                                      \
        _Pragma("unroll")                                                      \
        for (int h = 0; h < 4; h++) {                                          \
            const int nb2 = (nw + h * 8 + g) * 36 + k + t;                     \
            Bh[h][0] = __float_as_uint((sBh)[nb2]);                            \
            Bh[h][1] = __float_as_uint((sBh)[nb2 + 4]);                        \
            Bl[h][0] = __float_as_uint((sBl)[nb2]);                            \
            Bl[h][1] = __float_as_uint((sBl)[nb2 + 4]);                        \
        }                                                                      \
        _Pragma("unroll")                                                      \
        for (int f = 0; f < 4; f++)                                            \
            _Pragma("unroll")                                                  \
            for (int h = 0; h < 4; h++) {                                      \
                mma8(acc[f][h], Ah[f], Bh[h]);                                 \
                mma8(acc[f][h], Ah[f], Bl[h]);                                 \
                mma8(acc[f][h], Al[f], Bh[h]);                                 \
            }                                                                  \
    }

// ===========================================================================
// mm_gemm: batched D(128x128 tile) = A(128,K=256) x B^T (operands symmetric
// so this equals A@B). tf32 split-2 mma.sync, double-buffered pipelined.
// z<NB: (A1,B1,D1); z>=NB: (A2,B2,D2).
// epi 0: D=P; 1: D=1.5I-0.5P; 2: D=P*rsqrt(tr_now); 3: fused SICE on D(=L).
// Diagonal tiles (mi==nj) write trace partials trp[b*2+mi] when trp!=null.
// grid (2, 2, NB or 2NB), 256 threads, MM_SMEM dynamic smem.
// ===========================================================================
__global__ __launch_bounds__(256, 1) void mm_gemm(
    const float* __restrict__ A1, const float* __restrict__ B1, float* __restrict__ D1,
    const float* __restrict__ A2, const float* __restrict__ B2, float* __restrict__ D2,
    const float* __restrict__ tr_now, int epi, const float* __restrict__ Cn, float dec,
    float* __restrict__ trp)
{
    extern __shared__ float Sf[];
    const int z = blockIdx.z;
    const int b = z & (NB - 1);
    const float* Ab = ((z >= NB) ? A2 : A1) + (size_t)b * MAT;
    const float* Bb = ((z >= NB) ? B2 : B1) + (size_t)b * MAT;
    float* Dp = ((z >= NB) ? D2 : D1) + (size_t)b * MAT;
    const int mi = blockIdx.y, nj = blockIdx.x;
    const int m0 = mi * 128, n0 = nj * 128;

    const int tid = threadIdx.x;
    const int wid = tid >> 5, lane = tid & 31;
    const int g = lane >> 2, t = lane & 3;
    const int wm = wid >> 2, wn = wid & 3;
    const int mw = wm * 64, nw = wn * 32;
    const int srow = tid >> 3, sq = tid & 7;

    float4 pa[4], pb[4];
    float acc[4][4][4] = {};

    // prefetch chunk 0
    #pragma unroll
    for (int p = 0; p < 4; p++) {
        const int row = srow + p * 32;
        pa[p] = *(const float4*)(Ab + (size_t)(m0 + row) * DD + sq * 4);
        pb[p] = *(const float4*)(Bb + (size_t)(n0 + row) * DD + sq * 4);
    }
    // store stage 0
    {
        float* sAh = Sf; float* sAl = Sf + 4608;
        float* sBh = Sf + 9216; float* sBl = Sf + 13824;
        #pragma unroll
        for (int p = 0; p < 4; p++) {
            const int row = srow + p * 32;
            float4 hi, lo;
            split4(pa[p], hi, lo);
            *(float4*)(sAh + row * 36 + sq * 4) = hi;
            *(float4*)(sAl + row * 36 + sq * 4) = lo;
            split4(pb[p], hi, lo);
            *(float4*)(sBh + row * 36 + sq * 4) = hi;
            *(float4*)(sBl + row * 36 + sq * 4) = lo;
        }
    }
    __syncthreads();

    for (int c = 0; c < 8; c++) {
        if (c < 7) {
            const int k0 = (c + 1) * 32;
            #pragma unroll
            for (int p = 0; p < 4; p++) {
                const int row = srow + p * 32;
                pa[p] = *(const float4*)(Ab + (size_t)(m0 + row) * DD + k0 + sq * 4);
                pb[p] = *(const float4*)(Bb + (size_t)(n0 + row) * DD + k0 + sq * 4);
            }
        }
        {
            float* base = Sf + (c & 1) * STG;
            float* sAh = base; float* sAl = base + 4608;
            float* sBh = base + 9216; float* sBl = base + 13824;
            FRAG_COMPUTE(sAh, sAl, sBh, sBl);
        }
        if (c < 7) {
            float* base = Sf + ((c + 1) & 1) * STG;
            float* sAh = base; float* sAl = base + 4608;
            float* sBh = base + 9216; float* sBl = base + 13824;
            #pragma unroll
            for (int p = 0; p < 4; p++) {
                const int row = srow + p * 32;
                float4 hi, lo;
                split4(pa[p], hi, lo);
                *(float4*)(sAh + row * 36 + sq * 4) = hi;
                *(float4*)(sAl + row * 36 + sq * 4) = lo;
                split4(pb[p], hi, lo);
                *(float4*)(sBh + row * 36 + sq * 4) = hi;
                *(float4*)(sBl + row * 36 + sq * 4) = lo;
            }
            __syncthreads();
        }
    }

    // ---- epilogue ----
    const float rs = (epi == 2) ? rsqrtf(tr_now[b]) : 1.0f;
    const float* Cb = (epi == 3) ? (Cn + (size_t)b * MAT) : nullptr;
    float dsum = 0.f;
    const bool diag = (trp != nullptr) && (mi == nj);
    #pragma unroll
    for (int f = 0; f < 4; f++) {
        const int r0 = m0 + mw + f * 16 + g;
        const int r1 = r0 + 8;
        #pragma unroll
        for (int h = 0; h < 4; h++) {
            const int c = n0 + nw + h * 8 + 2 * t;
            float v[4] = {acc[f][h][0], acc[f][h][1], acc[f][h][2], acc[f][h][3]};
            const int rr[4] = {r0, r0, r1, r1};
            const int cc[4] = {c, c + 1, c, c + 1};
            if (epi == 1) {
                #pragma unroll
                for (int j = 0; j < 4; j++)
                    v[j] = ((rr[j] == cc[j]) ? 1.5f : 0.0f) - 0.5f * v[j];
            } else if (epi == 2) {
                #pragma unroll
                for (int j = 0; j < 4; j++) v[j] *= rs;
            } else if (epi == 3) {
                #pragma unroll
                for (int j = 0; j < 4; j++) {
                    float Lv = Dp[(size_t)rr[j] * DD + cc[j]];
                    float gg = Cb[(size_t)rr[j] * DD + cc[j]] - v[j];
                    v[j] = sice_f(Lv, gg, dec);
                }
            }
            if (diag) {
                #pragma unroll
                for (int j = 0; j < 4; j++)
                    if (rr[j] == cc[j]) dsum += v[j];
            }
            *(float2*)(Dp + (size_t)r0 * DD + c) = make_float2(v[0], v[1]);
            *(float2*)(Dp + (size_t)r1 * DD + c) = make_float2(v[2], v[3]);
        }
    }

    if (diag) {
        __syncthreads();
        Sf[tid] = dsum;
        __syncthreads();
        if (tid == 0) {
            float s2 = 0.f;
            for (int u = 0; u < 256; u++) s2 += Sf[u];
            trp[b * 2 + mi] = s2;
        }
    }
}

// ===========================================================================
// conv_mma: y[b] (256x784) = w (256x2048) @ x[b] (2048x784), tf32 split-2.
// A=w staged k-major (as mm_gemm); B=x transposed in staging to n-major
// [n][k] pitch 36 (coalesced scalar LDG along n; conflict-free STS.128).
// grid (7, 2, NB), 256 threads, MM_SMEM dynamic smem. 64 K-chunks.
// ===========================================================================
__global__ __launch_bounds__(256, 1) void conv_mma(
    const float* __restrict__ x, const float* __restrict__ w, float* __restrict__ y)
{
    extern __shared__ float Sf[];
    const int b = blockIdx.z;
    const int mi = blockIdx.y, nj = blockIdx.x;
    const int m0 = mi * 128, n0 = nj * 128;
    const float* Bx = x + (size_t)b * CINc * MMs;
    float* Dp = y + (size_t)b * DD * MMs;

    const int tid = threadIdx.x;
    const int wid = tid >> 5, lane = tid & 31;
    const int g = lane >> 2, t = lane & 3;
    const int wm = wid >> 2, wn = wid & 3;
    const int mw = wm * 64, nw = wn * 32;
    const int srow = tid >> 3, sq = tid & 7;          // A staging
    const int bn = tid & 127, bkh = tid >> 7;         // B staging: n-row, k-half
    const bool bvalid = (n0 + bn) < MMs;

    float4 pa[4];
    float pbv[16];
    float acc[4][4][4] = {};

    // prefetch chunk 0
    #pragma unroll
    for (int p = 0; p < 4; p++) {
        const int row = srow + p * 32;
        pa[p] = *(const float4*)(w + (size_t)(m0 + row) * CINc + sq * 4);
    }
    #pragma unroll
    for (int q = 0; q < 16; q++) {
        const int kk = bkh * 16 + q;
        pbv[q] = bvalid ? Bx[(size_t)kk * MMs + n0 + bn] : 0.f;
    }
    // store stage 0
    {
        float* sAh = Sf; float* sAl = Sf + 4608;
        float* sBh = Sf + 9216; float* sBl = Sf + 13824;
        #pragma unroll
        for (int p = 0; p < 4; p++) {
            const int row = srow + p * 32;
            float4 hi, lo;
            split4(pa[p], hi, lo);
            *(float4*)(sAh + row * 36 + sq * 4) = hi;
            *(float4*)(sAl + row * 36 + sq * 4) = lo;
        }
        #pragma unroll
        for (int q4 = 0; q4 < 4; q4++) {
            float4 v = make_float4(pbv[q4*4], pbv[q4*4+1], pbv[q4*4+2], pbv[q4*4+3]);
            float4 hi, lo;
            split4(v, hi, lo);
            *(float4*)(sBh + bn * 36 + bkh * 16 + q4 * 4) = hi;
            *(float4*)(sBl + bn * 36 + bkh * 16 + q4 * 4) = lo;
        }
    }
    __syncthreads();

    const int NCH = CINc / 32;   // 64
    for (int c = 0; c < NCH; c++) {
        if (c + 1 < NCH) {
            const int k0 = (c + 1) * 32;
            #pragma unroll
            for (int p = 0; p < 4; p++) {
                const int row = srow + p * 32;
                pa[p] = *(const float4*)(w + (size_t)(m0 + row) * CINc + k0 + sq * 4);
            }
            #pragma unroll
            for (int q = 0; q < 16; q++) {
                const int kk = bkh * 16 + q;
                pbv[q] = bvalid ? Bx[(size_t)(k0 + kk) * MMs + n0 + bn] : 0.f;
            }
        }
        {
            float* base = Sf + (c & 1) * STG;
            float* sAh = base; float* sAl = base + 4608;
            float* sBh = base + 9216; float* sBl = base + 13824;
            FRAG_COMPUTE(sAh, sAl, sBh, sBl);
        }
        if (c + 1 < NCH) {
            float* base = Sf + ((c + 1) & 1) * STG;
            float* sAh = base; float* sAl = base + 4608;
            float* sBh = base + 9216; float* sBl = base + 13824;
            #pragma unroll
            for (int p = 0; p < 4; p++) {
                const int row = srow + p * 32;
                float4 hi, lo;
                split4(pa[p], hi, lo);
                *(float4*)(sAh + row * 36 + sq * 4) = hi;
                *(float4*)(sAl + row * 36 + sq * 4) = lo;
            }
            #pragma unroll
            for (int q4 = 0; q4 < 4; q4++) {
                float4 v = make_float4(pbv[q4*4], pbv[q4*4+1], pbv[q4*4+2], pbv[q4*4+3]);
                float4 hi, lo;
                split4(v, hi, lo);
                *(float4*)(sBh + bn * 36 + bkh * 16 + q4 * 4) = hi;
                *(float4*)(sBl + bn * 36 + bkh * 16 + q4 * 4) = lo;
            }
            __syncthreads();
        }
    }

    // epilogue: plain store to y (stride MMs), guard n < 784
    #pragma unroll
    for (int f = 0; f < 4; f++) {
        const int r0 = m0 + mw + f * 16 + g;
        const int r1 = r0 + 8;
        #pragma unroll
        for (int h = 0; h < 4; h++) {
            const int c = n0 + nw + h * 8 + 2 * t;
            if (c < MMs) {
                *(float2*)(Dp + (size_t)r0 * MMs + c) =
                    make_float2(acc[f][h][0], acc[f][h][1]);
                *(float2*)(Dp + (size_t)r1 * MMs + c) =
                    make_float2(acc[f][h][2], acc[f][h][3]);
            }
        }
    }
}

// ===========================================================================
// FFMA kernels: BN, covariance (R5 verbatim)
// ===========================================================================
#define GEMM_COMPUTE(AsB, BsB)                                                 \
    {                                                                          \
        _Pragma("unroll")                                                      \
        for (int kk = 0; kk < KC; kk++) {                                      \
            float4 a0 = *(const float4*)(&(AsB)[kk][tr8 * 8]);                 \
            float4 a1 = *(const float4*)(&(AsB)[kk][tr8 * 8 + 4]);             \
            float4 bv = *(const float4*)(&(BsB)[kk][tc * 4]);                  \
            float ar[8] = {a0.x,a0.y,a0.z,a0.w,a1.x,a1.y,a1.z,a1.w};           \
            float br[4] = {bv.x,bv.y,bv.z,bv.w};                               \
            _Pragma("unroll")                                                  \
            for (int i = 0; i < 8; i++)                                        \
                _Pragma("unroll")                                              \
                for (int j = 0; j < 4; j++)                                    \
                    acc[i][j] = fmaf(ar[i], br[j], acc[i][j]);                 \
        }                                                                      \
    }

__global__ void bn_stats(const float* __restrict__ y, float* __restrict__ mean,
                         float* __restrict__ rstd)
{
    const int d = blockIdx.x;
    const int t = threadIdx.x;
    float s = 0.f, s2 = 0.f;
    for (int b = 0; b < NB; b++) {
        const float* p = y + (size_t)b * DD * MMs + (size_t)d * MMs;
        for (int m = t; m < MMs; m += 256) { float v = p[m]; s += v; s2 = fmaf(v, v, s2); }
    }
    __shared__ float sh1[8], sh2[8];
    const int lane = t & 31, wid = t >> 5;
    s = warpReduce(s); s2 = warpReduce(s2);
    if (lane == 0) { sh1[wid] = s; sh2[wid] = s2; }
    __syncthreads();
    if (wid == 0) {
        s  = (lane < 8) ? sh1[lane] : 0.f;
        s2 = (lane < 8) ? sh2[lane] : 0.f;
        s = warpReduce(s); s2 = warpReduce(s2);
        if (lane == 0) {
            const float N = (float)(NB * MMs);
            float mu  = s / N;
            float var = s2 / N - mu * mu;
            mean[d] = mu;
            rstd[d] = rsqrtf(var + 1e-5f);
        }
    }
}

__global__ void bn_apply(float* __restrict__ y, const float* __restrict__ mean,
                         const float* __restrict__ rstd, const float* __restrict__ gamma,
                         const float* __restrict__ beta, float* __restrict__ rowmean)
{
    const int bd = blockIdx.x;
    const int d  = bd & (DD - 1);
    float* p = y + (size_t)bd * MMs;
    const float mu = mean[d], rs = rstd[d], g = gamma[d], be = beta[d];
    const int t = threadIdx.x;
    float s = 0.f;
    for (int m = t; m < MMs; m += 256) {
        float v = fmaf((p[m] - mu) * rs, g, be);
        v = fmaxf(v, 0.f);
        p[m] = v;
        s += v;
    }
    __shared__ float sh[8];
    const int lane = t & 31, wid = t >> 5;
    s = warpReduce(s);
    if (lane == 0) sh[wid] = s;
    __syncthreads();
    if (wid == 0) {
        s = (lane < 8) ? sh[lane] : 0.f;
        s = warpReduce(s);
        if (lane == 0) rowmean[bd] = s * (1.0f / MMs);
    }
}

__global__ void cov_sym(
    const float* __restrict__ y, const float* __restrict__ rowmean, float* __restrict__ C)
{
    const int b = blockIdx.z;
    int ti, tj; tilemap(blockIdx.x, ti, tj);
    const int i0 = ti * 64, j0 = tj * 64;
    const float* Yb = y + (size_t)b * DD * MMs;

    __shared__ float Is[2][KC][68];
    __shared__ float Js[2][KC][68];
    const int tid = threadIdx.x;
    const int tc = tid & 15, tr8 = tid >> 4;

    float4 pa[2], pb[2];
    float acc[8][4] = {};

    #pragma unroll
    for (int h = 0; h < 2; h++) {
        int fi = tid + 128 * h;
        int row = fi >> 2, q = fi & 3;
        pa[h] = *(const float4*)(Yb + (size_t)(i0 + row) * MMs + q * 4);
        pb[h] = *(const float4*)(Yb + (size_t)(j0 + row) * MMs + q * 4);
    }
    #pragma unroll
    for (int h = 0; h < 2; h++) {
        int fi = tid + 128 * h;
        int row = fi >> 2, q = fi & 3;
        Is[0][q*4+0][row] = pa[h].x; Is[0][q*4+1][row] = pa[h].y;
        Is[0][q*4+2][row] = pa[h].z; Is[0][q*4+3][row] = pa[h].w;
        Js[0][q*4+0][row] = pb[h].x; Js[0][q*4+1][row] = pb[h].y;
        Js[0][q*4+2][row] = pb[h].z; Js[0][q*4+3][row] = pb[h].w;
    }
    __syncthreads();

    const int NCH = MMs / KC;
    for (int ch = 0; ch < NCH; ch++) {
        const int buf = ch & 1;
        if (ch + 1 < NCH) {
            const int k0 = (ch + 1) * KC;
            #pragma unroll
            for (int h = 0; h < 2; h++) {
                int fi = tid + 128 * h;
                int row = fi >> 2, q = fi & 3;
                pa[h] = *(const float4*)(Yb + (size_t)(i0 + row) * MMs + k0 + q * 4);
                pb[h] = *(const float4*)(Yb + (size_t)(j0 + row) * MMs + k0 + q * 4);
            }
        }
        GEMM_COMPUTE(Is[buf], Js[buf]);
        if (ch + 1 < NCH) {
            const int nb = buf ^ 1;
            #pragma unroll
            for (int h = 0; h < 2; h++) {
                int fi = tid + 128 * h;
                int row = fi >> 2, q = fi & 3;
                Is[nb][q*4+0][row] = pa[h].x; Is[nb][q*4+1][row] = pa[h].y;
                Is[nb][q*4+2][row] = pa[h].z; Is[nb][q*4+3][row] = pa[h].w;
                Js[nb][q*4+0][row] = pb[h].x; Js[nb][q*4+1][row] = pb[h].y;
                Js[nb][q*4+2][row] = pb[h].z; Js[nb][q*4+3][row] = pb[h].w;
            }
            __syncthreads();
        }
    }

    const float invM = 1.0f / (float)MMs;
    const float* mu = rowmean + b * DD;
    float* Cb = C + (size_t)b * MAT;
    #pragma unroll
    for (int i = 0; i < 8; i++) {
        const int r = i0 + tr8 * 8 + i;
        const float mi = mu[r];
        const int c0 = j0 + tc * 4;
        float v[4];
        #pragma unroll
        for (int j = 0; j < 4; j++) v[j] = acc[i][j] * invM - mi * mu[c0 + j];
        *(float4*)(Cb + (size_t)r * DD + c0) = make_float4(v[0], v[1], v[2], v[3]);
        if (ti != tj) {
            #pragma unroll
            for (int j = 0; j < 4; j++) Cb[(size_t)(c0+j) * DD + r] = v[j];
        }
    }
}

// ---------------------------------------------------------------------------
// small kernels
// ---------------------------------------------------------------------------
__global__ void tracek0(const float* __restrict__ X, const float* __restrict__ jitter,
                        float* __restrict__ tr0, float* __restrict__ jcp)
{
    const int b = blockIdx.x;
    const int t = threadIdx.x;
    float v = X[(size_t)b * MAT + t * 257];
    float jt = 1e-10f + 1e-9f * jitter[t];
    __shared__ float sh[8], shj[8];
    const int lane = t & 31, wid = t >> 5;
    v = warpReduce(v); jt = warpReduce(jt);
    if (lane == 0) { sh[wid] = v; shj[wid] = jt; }
    __syncthreads();
    if (wid == 0) {
        v  = (lane < 8) ? sh[lane]  : 0.f;
        jt = (lane < 8) ? shj[lane] : 0.f;
        v = warpReduce(v); jt = warpReduce(jt);
        if (lane == 0) {
            tr0[b] = v;
            if (b == 0) *jcp = jt;
        }
    }
}

__global__ void scalek(float* __restrict__ C, const float* __restrict__ tr0)
{
    const int idx = blockIdx.x * 256 + threadIdx.x;
    C[idx] *= (1.0f / tr0[idx >> 16]);
}

__global__ void prep_ns(const float* __restrict__ Sm, const float* __restrict__ jitter,
                        const float* __restrict__ trp, const float* __restrict__ jcp,
                        float* __restrict__ A, float* __restrict__ ZY,
                        float* __restrict__ tr_now)
{
    const int idx = blockIdx.x * 256 + threadIdx.x;
    const int b = idx >> 16, rc = idx & 65535, r = rc >> 8, c = rc & 255;
    const float jc = *jcp;
    float t;
    if (trp != nullptr) t = trp[b*2+0] + trp[b*2+1] + jc;
    else                t = 1.0f + jc;
    float v = Sm[idx];
    if (r == c) v += 1e-10f + 1e-9f * jitter[r];
    float a = v * (1.0f / t);
    A[idx] = a;
    ZY[idx] = (r == c ? 1.5f : 0.0f) - 0.5f * a;
    if (rc == 0) tr_now[b] = t;
}

__global__ void gather_out(const float* __restrict__ L, const float* __restrict__ trp,
                           float* __restrict__ out)
{
    const int b = blockIdx.y, i = blockIdx.x, j = threadIdx.x;
    if (j < i) return;
    const float t = trp[b*2+0] + trp[b*2+1];
    const float s = rsqrtf(t);
    const int k = i * 256 - (i * (i - 1)) / 2 + (j - i);
    out[(size_t)b * 32896 + k] = L[(size_t)b * MAT + i * 256 + j] * s;
}

// ---------------------------------------------------------------------------
// Host orchestration
// ---------------------------------------------------------------------------
static void run_inv(const float* Sm, const float* jitter, const float* trp_in,
                    float* zz, float* tr_now, const float* jcp,
                    float* A, float* Y, float* Z, float* Y2, float* Z2, float* ZYt)
{
    const dim3 g1(2, 2, NB);
    const dim3 g2(2, 2, 2 * NB);
    const float* FN = nullptr;
    float* FNm = nullptr;
    prep_ns<<<BMAT / 256, 256>>>(Sm, jitter, trp_in, jcp, A, Z, tr_now);   // Z = ZY0
    mm_gemm<<<g1, 256, MM_SMEM>>>(A, Z, Y, FN, FN, FNm, tr_now, 0, FN, 0.f, FNm);
    float *Yc = Y, *Zc = Z, *Ya = Y2, *Za = Z2;
    for (int it = 0; it < 5; it++) {
        mm_gemm<<<g1, 256, MM_SMEM>>>(Zc, Yc, ZYt, FN, FN, FNm, tr_now, 1, FN, 0.f, FNm);
        mm_gemm<<<g2, 256, MM_SMEM>>>(Yc, ZYt, Ya, ZYt, Zc, Za, tr_now, 0, FN, 0.f, FNm);
        float* t1 = Yc; Yc = Ya; Ya = t1;
        float* t2 = Zc; Zc = Za; Za = t2;
    }
    mm_gemm<<<g1, 256, MM_SMEM>>>(Zc, Yc, ZYt, FN, FN, FNm, tr_now, 1, FN, 0.f, FNm);
    mm_gemm<<<g1, 256, MM_SMEM>>>(ZYt, Zc, zz, FN, FN, FNm, tr_now, 2, FN, 0.f, FNm);
}

extern "C" void kernel_launch(void* const* d_in, const int* in_sizes, int n_in,
                              void* d_out, int out_size)
{
    (void)in_sizes; (void)n_in; (void)out_size;
    const float* x      = (const float*)d_in[0];
    const float* w      = (const float*)d_in[1];
    const float* gamma  = (const float*)d_in[2];
    const float* beta   = (const float*)d_in[3];
    const float* jitter = (const float*)d_in[4];
    float* out = (float*)d_out;

    cudaFuncSetAttribute(mm_gemm, cudaFuncAttributeMaxDynamicSharedMemorySize, MM_SMEM);
    cudaFuncSetAttribute(conv_mma, cudaFuncAttributeMaxDynamicSharedMemorySize, MM_SMEM);

    float *y, *mats, *small;
    cudaGetSymbolAddress((void**)&y, g_y);
    cudaGetSymbolAddress((void**)&mats, g_mats);
    cudaGetSymbolAddress((void**)&small, g_small);

    float* Cn  = mats + 0u * BMAT;
    float* A   = mats + 1u * BMAT;
    float* Y   = mats + 2u * BMAT;
    float* Z   = mats + 3u * BMAT;
    float* Y2  = mats + 4u * BMAT;
    float* Z2  = mats + 5u * BMAT;
    float* ZYt = mats + 6u * BMAT;
    float* zz  = mats + 7u * BMAT;
    float* LLT = mats + 8u * BMAT;

    float* bn_mean = small;
    float* bn_rstd = small + 256;
    float* rowmean = small + 512;
    float* tr0     = small + 8704;
    float* tr_now  = small + 8736;
    float* jcp     = small + 8768;
    float* trp     = small + 8772;

    const dim3 g1(2, 2, NB);
    const float* FN = nullptr;
    float* FNm = nullptr;

    // Stage 1: conv (tensor) + BN + ReLU
    conv_mma<<<dim3(7, 2, NB), 256, MM_SMEM>>>(x, w, y);
    bn_stats<<<DD, 256>>>(y, bn_mean, bn_rstd);
    bn_apply<<<NB * DD, 256>>>(y, bn_mean, bn_rstd, gamma, beta, rowmean);

    // Stage 2: covariance + trace normalize (Cn == normalized C == sym_C)
    cov_sym<<<dim3(10, 1, NB), 128>>>(y, rowmean, Cn);
    tracek0<<<NB, 256>>>(Cn, jitter, tr0, jcp);
    scalek<<<BMAT / 256, 256>>>(Cn, tr0);

    // Stage 3: LLT = inv_sqrtm(Cn + Ij)^2 ; tr(Cn+Ij) = 1 + jc analytically
    run_inv(Cn, jitter, nullptr, zz, tr_now, jcp, A, Y, Z, Y2, Z2, ZYt);
    mm_gemm<<<g1, 256, MM_SMEM>>>(zz, zz, LLT, FN, FN, FNm, tr_now, 0, FN, 0.f, trp);

    // Stage 4: SICE loop (i=2 has dec==0 -> exact identity, skipped)
    for (int i = 0; i < 2; i++) {
        run_inv(LLT, jitter, trp, zz, tr_now, jcp, A, Y, Z, Y2, Z2, ZYt);
        const float dec = 5.0f * (1.0f - (float)i / 2.0f);
        mm_gemm<<<g1, 256, MM_SMEM>>>(zz, zz, LLT, FN, FN, FNm, tr_now, 3, Cn, dec, trp);
    }

    // Stage 5: triuvec with trace from final epi3 partials
    gather_out<<<dim3(DD, NB), 256>>>(LLT, trp, out);
}